// round 9
// baseline (speedup 1.0000x reference)
#include <cuda_runtime.h>

#define N_NODES 50000
#define N_EDGES 600000
#define D 128

// ---------------------------------------------------------------------------
// Scratch (allocation-free rule: device globals)
// ---------------------------------------------------------------------------
__device__ float g_h[(size_t)N_NODES * D];     // activations
__device__ float g_agg[(size_t)N_NODES * D];   // aggregation buffer / Y buffer
__device__ float g_dout[N_NODES];              // deg_out^{-1/2}
__device__ float g_din[N_NODES];               // deg_in^{-1/2}
__device__ int   g_cnt_out[N_NODES];
__device__ int   g_cnt_in[N_NODES];
__device__ int   g_cursor[N_NODES];
__device__ int   g_offs[N_NODES + 1];
__device__ int   g_csr_src[N_EDGES];

// ---------------------------------------------------------------------------
// Degree histograms
// ---------------------------------------------------------------------------
__global__ void deg_zero_kernel() {
    int i = blockIdx.x * blockDim.x + threadIdx.x;
    if (i < N_NODES) { g_cnt_out[i] = 0; g_cnt_in[i] = 0; g_cursor[i] = 0; }
}

__global__ void deg_count_kernel(const int* __restrict__ src,
                                 const int* __restrict__ dst) {
    int e = blockIdx.x * blockDim.x + threadIdx.x;
    if (e < N_EDGES) {
        atomicAdd(&g_cnt_out[src[e]], 1);
        atomicAdd(&g_cnt_in[dst[e]], 1);
    }
}

// ---------------------------------------------------------------------------
// Exclusive scan of in-degree -> g_offs, plus din/dout finalize (fused).
// ---------------------------------------------------------------------------
__global__ void scan_kernel() {
    __shared__ int sums[1024];
    const int CH = (N_NODES + 1023) / 1024;   // 49
    int t = threadIdx.x;
    int base = t * CH;
    int s = 0;
    for (int i = 0; i < CH; i++) {
        int idx = base + i;
        if (idx < N_NODES) s += g_cnt_in[idx];
    }
    sums[t] = s;
    __syncthreads();
    for (int off = 1; off < 1024; off <<= 1) {
        int v = (t >= off) ? sums[t - off] : 0;
        __syncthreads();
        sums[t] += v;
        __syncthreads();
    }
    int excl = (t == 0) ? 0 : sums[t - 1];
    for (int i = 0; i < CH; i++) {
        int idx = base + i;
        if (idx < N_NODES) {
            g_offs[idx] = excl;
            int ci = g_cnt_in[idx];
            excl += ci;
            g_din[idx]  = rsqrtf((float)max(ci, 1));
            g_dout[idx] = rsqrtf((float)max(g_cnt_out[idx], 1));
        }
    }
    if (t == 1023) g_offs[N_NODES] = excl;
}

// ---------------------------------------------------------------------------
// Fill CSR (dst-bucketed; within-bucket order arbitrary)
// ---------------------------------------------------------------------------
__global__ void fill_kernel(const int* __restrict__ src,
                            const int* __restrict__ dst) {
    int e = blockIdx.x * blockDim.x + threadIdx.x;
    if (e < N_EDGES) {
        int d = dst[e];
        int pos = g_offs[d] + atomicAdd(&g_cursor[d], 1);
        g_csr_src[pos] = src[e];
    }
}

// ---------------------------------------------------------------------------
// Layer-1 prologue: g_h = features * dout^{-1/2} (row-wise).
// Doubles as an L2 prefetch: the write-allocate of g_h makes the following
// random gather hit L2 instead of DRAM (removing this cost +50us in R4/R7).
// ---------------------------------------------------------------------------
__global__ void scale_kernel(const float* __restrict__ feat) {
    int i = blockIdx.x * blockDim.x + threadIdx.x;
    if (i < N_NODES * D) g_h[i] = feat[i] * g_dout[i >> 7];   // D == 128
}

// ---------------------------------------------------------------------------
// 128-wide gather aggregation: warp per dst node, lane l owns floats [4l,4l+4).
// Unroll 4 with independent accumulators (Round-2 proven body).
// ---------------------------------------------------------------------------
__global__ void agg_kernel(const float* __restrict__ in) {
    int gtid = blockIdx.x * blockDim.x + threadIdx.x;
    int node = gtid >> 5;
    int lane = gtid & 31;
    if (node >= N_NODES) return;
    int beg = g_offs[node];
    int end = g_offs[node + 1];

    float4 a0 = {0.f, 0.f, 0.f, 0.f};
    float4 a1 = a0, a2 = a0, a3 = a0;

    int i = beg;
    for (; i + 4 <= end; i += 4) {
        int s0 = g_csr_src[i + 0];
        int s1 = g_csr_src[i + 1];
        int s2 = g_csr_src[i + 2];
        int s3 = g_csr_src[i + 3];
        float4 v0 = ((const float4*)(in + (size_t)s0 * D))[lane];
        float4 v1 = ((const float4*)(in + (size_t)s1 * D))[lane];
        float4 v2 = ((const float4*)(in + (size_t)s2 * D))[lane];
        float4 v3 = ((const float4*)(in + (size_t)s3 * D))[lane];
        a0.x += v0.x; a0.y += v0.y; a0.z += v0.z; a0.w += v0.w;
        a1.x += v1.x; a1.y += v1.y; a1.z += v1.z; a1.w += v1.w;
        a2.x += v2.x; a2.y += v2.y; a2.z += v2.z; a2.w += v2.w;
        a3.x += v3.x; a3.y += v3.y; a3.z += v3.z; a3.w += v3.w;
    }
    for (; i < end; i++) {
        int s = g_csr_src[i];
        float4 v = ((const float4*)(in + (size_t)s * D))[lane];
        a0.x += v.x; a0.y += v.y; a0.z += v.z; a0.w += v.w;
    }
    float4 r;
    r.x = (a0.x + a1.x) + (a2.x + a3.x);
    r.y = (a0.y + a1.y) + (a2.y + a3.y);
    r.z = (a0.z + a1.z) + (a2.z + a3.z);
    r.w = (a0.w + a1.w) + (a2.w + a3.w);
    ((float4*)(g_agg + (size_t)node * D))[lane] = r;
}

// ---------------------------------------------------------------------------
// Register-tiled GEMM (Round-2 proven): C[N,128] = A[N,128] @ W[128,128].
// Tile 64 rows x 128 cols per block (256 threads), 4x8 outputs per thread
// (cols tx + 16j). Epilogue: *din, +bias, relu, *dout.
// ---------------------------------------------------------------------------
template <bool RELU, bool SCALE_OUT>
__global__ __launch_bounds__(256)
void gemm128_kernel(const float* __restrict__ A,
                    const float* __restrict__ W,
                    const float* __restrict__ bias,
                    float* __restrict__ out)
{
    __shared__ float As[32][68];     // k-major [k][row]
    __shared__ float Ws[32][128];

    const int tid = threadIdx.x;
    const int tx = tid & 15;         // col group: cols tx + 16j
    const int ty = tid >> 4;         // row group: rows ty*4 .. ty*4+3
    const int row0 = blockIdx.x * 64;

    float acc[4][8];
    #pragma unroll
    for (int r = 0; r < 4; r++)
        #pragma unroll
        for (int c = 0; c < 8; c++) acc[r][c] = 0.0f;

    for (int kc = 0; kc < D; kc += 32) {
        // A chunk: 64 rows x 32 k, stored transposed (k-major)
        #pragma unroll
        for (int j = 0; j < 2; j++) {
            int f = j * 256 + tid;           // 0..511
            int r = f >> 3;
            int kk = (f & 7) << 2;
            int grow = row0 + r;
            float4 v = make_float4(0.f, 0.f, 0.f, 0.f);
            if (grow < N_NODES)
                v = ((const float4*)(A + (size_t)grow * D + kc))[f & 7];
            As[kk + 0][r] = v.x;
            As[kk + 1][r] = v.y;
            As[kk + 2][r] = v.z;
            As[kk + 3][r] = v.w;
        }
        // W chunk: 32 k x 128 cols, row-major
        #pragma unroll
        for (int j = 0; j < 4; j++) {
            int f = j * 256 + tid;           // 0..1023
            int k = f >> 5;
            int c = (f & 31) << 2;
            *(float4*)&Ws[k][c] = *(const float4*)(W + (size_t)(kc + k) * D + c);
        }
        __syncthreads();

        #pragma unroll
        for (int k = 0; k < 32; k++) {
            float4 a = *(const float4*)&As[k][ty * 4];
            float wv[8];
            #pragma unroll
            for (int j = 0; j < 8; j++) wv[j] = Ws[k][tx + 16 * j];
            #pragma unroll
            for (int j = 0; j < 8; j++) {
                acc[0][j] += a.x * wv[j];
                acc[1][j] += a.y * wv[j];
                acc[2][j] += a.z * wv[j];
                acc[3][j] += a.w * wv[j];
            }
        }
        __syncthreads();
    }

    #pragma unroll
    for (int r = 0; r < 4; r++) {
        int grow = row0 + ty * 4 + r;
        if (grow < N_NODES) {
            float ds = g_din[grow];
            float os = SCALE_OUT ? g_dout[grow] : 1.0f;
            #pragma unroll
            for (int j = 0; j < 8; j++) {
                int c = tx + 16 * j;
                float v = acc[r][j] * ds + bias[c];
                if (RELU) v = fmaxf(v, 0.0f);
                out[(size_t)grow * D + c] = v * os;
            }
        }
    }
}

// ---------------------------------------------------------------------------
// Layer-3 pre-GEMM: Y[N,16] = A[N,128] @ W3[128,16]. W3 fully in smem.
// ---------------------------------------------------------------------------
__global__ __launch_bounds__(256)
void gemm16_kernel(const float* __restrict__ A,
                   const float* __restrict__ W3,
                   float* __restrict__ Y)
{
    __shared__ float Ws[128][20];    // padded: 80B row stride keeps float4 alignment
    int tid = threadIdx.x;
    for (int idx = tid; idx < 128 * 16; idx += 256) {
        int k = idx >> 4, c = idx & 15;
        Ws[k][c] = W3[idx];
    }
    __syncthreads();

    int row = blockIdx.x * 64 + (tid >> 2);
    int c4 = (tid & 3) << 2;
    if (row >= N_NODES) return;

    float4 acc = {0.f, 0.f, 0.f, 0.f};
    const float4* arow = (const float4*)(A + (size_t)row * D);
    #pragma unroll
    for (int kq = 0; kq < 32; kq++) {
        float4 a = arow[kq];
        float4 w0 = *(const float4*)&Ws[kq * 4 + 0][c4];
        float4 w1 = *(const float4*)&Ws[kq * 4 + 1][c4];
        float4 w2 = *(const float4*)&Ws[kq * 4 + 2][c4];
        float4 w3 = *(const float4*)&Ws[kq * 4 + 3][c4];
        acc.x += a.x * w0.x + a.y * w1.x + a.z * w2.x + a.w * w3.x;
        acc.y += a.x * w0.y + a.y * w1.y + a.z * w2.y + a.w * w3.y;
        acc.z += a.x * w0.z + a.y * w1.z + a.z * w2.z + a.w * w3.z;
        acc.w += a.x * w0.w + a.y * w1.w + a.z * w2.w + a.w * w3.w;
    }
    *(float4*)(Y + (size_t)row * 16 + c4) = acc;
}

// ---------------------------------------------------------------------------
// 16-wide aggregation + epilogue: out[n] = din[n] * segsum(Y[src]) + b3.
// ---------------------------------------------------------------------------
__global__ void agg16_kernel(const float* __restrict__ Y,
                             const float* __restrict__ b3,
                             float* __restrict__ out)
{
    int tid = threadIdx.x;
    int node = blockIdx.x * 64 + (tid >> 2);
    int q = tid & 3;
    if (node >= N_NODES) return;
    int beg = g_offs[node];
    int end = g_offs[node + 1];

    float4 a0 = {0.f, 0.f, 0.f, 0.f};
    float4 a1 = a0;
    int i = beg;
    for (; i + 2 <= end; i += 2) {
        int s0 = g_csr_src[i + 0];
        int s1 = g_csr_src[i + 1];
        float4 v0 = ((const float4*)(Y + (size_t)s0 * 16))[q];
        float4 v1 = ((const float4*)(Y + (size_t)s1 * 16))[q];
        a0.x += v0.x; a0.y += v0.y; a0.z += v0.z; a0.w += v0.w;
        a1.x += v1.x; a1.y += v1.y; a1.z += v1.z; a1.w += v1.w;
    }
    if (i < end) {
        int s = g_csr_src[i];
        float4 v = ((const float4*)(Y + (size_t)s * 16))[q];
        a0.x += v.x; a0.y += v.y; a0.z += v.z; a0.w += v.w;
    }
    float dn = g_din[node];
    float4 bb = ((const float4*)b3)[q];
    float4 o;
    o.x = (a0.x + a1.x) * dn + bb.x;
    o.y = (a0.y + a1.y) * dn + bb.y;
    o.z = (a0.z + a1.z) * dn + bb.z;
    o.w = (a0.w + a1.w) * dn + bb.w;
    ((float4*)(out + (size_t)node * 16))[q] = o;
}

// ---------------------------------------------------------------------------
// Launch
// ---------------------------------------------------------------------------
extern "C" void kernel_launch(void* const* d_in, const int* in_sizes, int n_in,
                              void* d_out, int out_size) {
    const float* features = (const float*)d_in[0];
    const int*   src      = (const int*)d_in[1];
    const int*   dst      = (const int*)d_in[2];
    const float* W1       = (const float*)d_in[3];
    const float* b1       = (const float*)d_in[4];
    const float* W2       = (const float*)d_in[5];
    const float* b2       = (const float*)d_in[6];
    const float* W3       = (const float*)d_in[7];
    const float* b3       = (const float*)d_in[8];
    float* out = (float*)d_out;

    float* h_ptr;
    float* agg_ptr;
    cudaGetSymbolAddress((void**)&h_ptr, g_h);
    cudaGetSymbolAddress((void**)&agg_ptr, g_agg);

    const int T = 256;
    int nodeBlocks = (N_NODES + T - 1) / T;
    int edgeBlocks = (N_EDGES + T - 1) / T;
    int elemBlocks = (N_NODES * D + T - 1) / T;
    int aggBlocks  = (N_NODES * 32 + T - 1) / T;     // warp per node
    int gemmBlocks = (N_NODES + 63) / 64;
    int rows64     = (N_NODES + 63) / 64;

    // CSR build + degrees
    deg_zero_kernel<<<nodeBlocks, T>>>();
    deg_count_kernel<<<edgeBlocks, T>>>(src, dst);
    scan_kernel<<<1, 1024>>>();
    fill_kernel<<<edgeBlocks, T>>>(src, dst);

    // ---- Layer 1 (explicit scale pass = L2 prefetch of the gather source) ----
    scale_kernel<<<elemBlocks, T>>>(features);
    agg_kernel<<<aggBlocks, T>>>(h_ptr);
    gemm128_kernel<true, true><<<gemmBlocks, 256>>>(agg_ptr, W1, b1, h_ptr);

    // ---- Layer 2 ----
    agg_kernel<<<aggBlocks, T>>>(h_ptr);
    gemm128_kernel<true, true><<<gemmBlocks, 256>>>(agg_ptr, W2, b2, h_ptr);

    // ---- Layer 3: GEMM first (16-wide), then aggregate ----
    gemm16_kernel<<<rows64, 256>>>(h_ptr, W3, agg_ptr);   // Y stored in g_agg
    agg16_kernel<<<rows64, 256>>>(agg_ptr, b3, out);
}

// round 10
// speedup vs baseline: 1.0604x; 1.0604x over previous
#include <cuda_runtime.h>
#include <cuda_fp16.h>

#define N_NODES 50000
#define N_EDGES 600000
#define D 128

// ---------------------------------------------------------------------------
// Scratch (allocation-free rule: device globals)
// ---------------------------------------------------------------------------
__device__ __half g_h16[(size_t)N_NODES * D];  // fp16 activations (gather source)
__device__ float  g_h32[(size_t)N_NODES * D];  // fp32 activations (layer-3 input)
__device__ float  g_agg[(size_t)N_NODES * D];  // aggregation buffer / Y buffer
__device__ float  g_dout[N_NODES];             // deg_out^{-1/2}
__device__ float  g_din[N_NODES];              // deg_in^{-1/2}
__device__ int    g_cnt_out[N_NODES];
__device__ int    g_cnt_in[N_NODES];
__device__ int    g_cursor[N_NODES];
__device__ int    g_offs[N_NODES + 1];
__device__ int    g_csr_src[N_EDGES];

// ---------------------------------------------------------------------------
// Degree histograms
// ---------------------------------------------------------------------------
__global__ void deg_zero_kernel() {
    int i = blockIdx.x * blockDim.x + threadIdx.x;
    if (i < N_NODES) { g_cnt_out[i] = 0; g_cnt_in[i] = 0; g_cursor[i] = 0; }
}

__global__ void deg_count_kernel(const int* __restrict__ src,
                                 const int* __restrict__ dst) {
    int e = blockIdx.x * blockDim.x + threadIdx.x;
    if (e < N_EDGES) {
        atomicAdd(&g_cnt_out[src[e]], 1);
        atomicAdd(&g_cnt_in[dst[e]], 1);
    }
}

// ---------------------------------------------------------------------------
// Exclusive scan of in-degree -> g_offs, plus din/dout finalize (fused).
// ---------------------------------------------------------------------------
__global__ void scan_kernel() {
    __shared__ int sums[1024];
    const int CH = (N_NODES + 1023) / 1024;   // 49
    int t = threadIdx.x;
    int base = t * CH;
    int s = 0;
    for (int i = 0; i < CH; i++) {
        int idx = base + i;
        if (idx < N_NODES) s += g_cnt_in[idx];
    }
    sums[t] = s;
    __syncthreads();
    for (int off = 1; off < 1024; off <<= 1) {
        int v = (t >= off) ? sums[t - off] : 0;
        __syncthreads();
        sums[t] += v;
        __syncthreads();
    }
    int excl = (t == 0) ? 0 : sums[t - 1];
    for (int i = 0; i < CH; i++) {
        int idx = base + i;
        if (idx < N_NODES) {
            g_offs[idx] = excl;
            int ci = g_cnt_in[idx];
            excl += ci;
            g_din[idx]  = rsqrtf((float)max(ci, 1));
            g_dout[idx] = rsqrtf((float)max(g_cnt_out[idx], 1));
        }
    }
    if (t == 1023) g_offs[N_NODES] = excl;
}

// ---------------------------------------------------------------------------
// Fill CSR (dst-bucketed; within-bucket order arbitrary)
// ---------------------------------------------------------------------------
__global__ void fill_kernel(const int* __restrict__ src,
                            const int* __restrict__ dst) {
    int e = blockIdx.x * blockDim.x + threadIdx.x;
    if (e < N_EDGES) {
        int d = dst[e];
        int pos = g_offs[d] + atomicAdd(&g_cursor[d], 1);
        g_csr_src[pos] = src[e];
    }
}

// ---------------------------------------------------------------------------
// Layer-1 prologue: g_h16 = fp16(features * dout^{-1/2}).
// Thread handles 4 consecutive floats -> 4 halves (one 8B store).
// ---------------------------------------------------------------------------
__global__ void scale_kernel(const float* __restrict__ feat) {
    int idx = blockIdx.x * blockDim.x + threadIdx.x;   // over N*32 float4 groups
    if (idx < N_NODES * (D / 4)) {
        float4 f = ((const float4*)feat)[idx];
        float w = g_dout[idx >> 5];                    // 32 groups per row
        __half2 lo = __floats2half2_rn(f.x * w, f.y * w);
        __half2 hi = __floats2half2_rn(f.z * w, f.w * w);
        ((__half2*)g_h16)[idx * 2 + 0] = lo;
        ((__half2*)g_h16)[idx * 2 + 1] = hi;
    }
}

// ---------------------------------------------------------------------------
// 128-wide gather aggregation over fp16 rows: warp per dst node,
// lane l owns cols [4l, 4l+4) (uint2 = 4 halves = 8B per edge per lane).
// Accumulate fp32. Unroll 4 with independent accumulators.
// ---------------------------------------------------------------------------
__global__ void agg_kernel(const __half* __restrict__ in) {
    int gtid = blockIdx.x * blockDim.x + threadIdx.x;
    int node = gtid >> 5;
    int lane = gtid & 31;
    if (node >= N_NODES) return;
    int beg = g_offs[node];
    int end = g_offs[node + 1];

    float4 a0 = {0.f, 0.f, 0.f, 0.f};
    float4 a1 = a0, a2 = a0, a3 = a0;

    int i = beg;
    for (; i + 4 <= end; i += 4) {
        int s0 = g_csr_src[i + 0];
        int s1 = g_csr_src[i + 1];
        int s2 = g_csr_src[i + 2];
        int s3 = g_csr_src[i + 3];
        uint2 u0 = ((const uint2*)(in + (size_t)s0 * D))[lane];
        uint2 u1 = ((const uint2*)(in + (size_t)s1 * D))[lane];
        uint2 u2 = ((const uint2*)(in + (size_t)s2 * D))[lane];
        uint2 u3 = ((const uint2*)(in + (size_t)s3 * D))[lane];
        float2 p, q;
        p = __half22float2(*(__half2*)&u0.x); q = __half22float2(*(__half2*)&u0.y);
        a0.x += p.x; a0.y += p.y; a0.z += q.x; a0.w += q.y;
        p = __half22float2(*(__half2*)&u1.x); q = __half22float2(*(__half2*)&u1.y);
        a1.x += p.x; a1.y += p.y; a1.z += q.x; a1.w += q.y;
        p = __half22float2(*(__half2*)&u2.x); q = __half22float2(*(__half2*)&u2.y);
        a2.x += p.x; a2.y += p.y; a2.z += q.x; a2.w += q.y;
        p = __half22float2(*(__half2*)&u3.x); q = __half22float2(*(__half2*)&u3.y);
        a3.x += p.x; a3.y += p.y; a3.z += q.x; a3.w += q.y;
    }
    for (; i < end; i++) {
        int s = g_csr_src[i];
        uint2 u = ((const uint2*)(in + (size_t)s * D))[lane];
        float2 p = __half22float2(*(__half2*)&u.x);
        float2 q = __half22float2(*(__half2*)&u.y);
        a0.x += p.x; a0.y += p.y; a0.z += q.x; a0.w += q.y;
    }
    float4 r;
    r.x = (a0.x + a1.x) + (a2.x + a3.x);
    r.y = (a0.y + a1.y) + (a2.y + a3.y);
    r.z = (a0.z + a1.z) + (a2.z + a3.z);
    r.w = (a0.w + a1.w) + (a2.w + a3.w);
    ((float4*)(g_agg + (size_t)node * D))[lane] = r;
}

// ---------------------------------------------------------------------------
// Register-tiled GEMM (Round-2 proven mainloop): C[N,128] = A[N,128]@W[128,128]
// Tile 64 rows x 128 cols per block (256 threads), 4x8 outputs per thread
// (cols tx + 16j). Epilogue: *din, +bias, relu, *dout; output type templated
// (fp16 for gather-source layers, fp32 for layer-3 input).
// ---------------------------------------------------------------------------
template <bool RELU, bool SCALE_OUT, typename OutT>
__global__ __launch_bounds__(256)
void gemm128_kernel(const float* __restrict__ A,
                    const float* __restrict__ W,
                    const float* __restrict__ bias,
                    OutT* __restrict__ out)
{
    __shared__ float As[32][68];     // k-major [k][row]
    __shared__ float Ws[32][128];

    const int tid = threadIdx.x;
    const int tx = tid & 15;         // col group: cols tx + 16j
    const int ty = tid >> 4;         // row group: rows ty*4 .. ty*4+3
    const int row0 = blockIdx.x * 64;

    float acc[4][8];
    #pragma unroll
    for (int r = 0; r < 4; r++)
        #pragma unroll
        for (int c = 0; c < 8; c++) acc[r][c] = 0.0f;

    for (int kc = 0; kc < D; kc += 32) {
        // A chunk: 64 rows x 32 k, stored transposed (k-major)
        #pragma unroll
        for (int j = 0; j < 2; j++) {
            int f = j * 256 + tid;           // 0..511
            int r = f >> 3;
            int kk = (f & 7) << 2;
            int grow = row0 + r;
            float4 v = make_float4(0.f, 0.f, 0.f, 0.f);
            if (grow < N_NODES)
                v = ((const float4*)(A + (size_t)grow * D + kc))[f & 7];
            As[kk + 0][r] = v.x;
            As[kk + 1][r] = v.y;
            As[kk + 2][r] = v.z;
            As[kk + 3][r] = v.w;
        }
        // W chunk: 32 k x 128 cols, row-major
        #pragma unroll
        for (int j = 0; j < 4; j++) {
            int f = j * 256 + tid;           // 0..1023
            int k = f >> 5;
            int c = (f & 31) << 2;
            *(float4*)&Ws[k][c] = *(const float4*)(W + (size_t)(kc + k) * D + c);
        }
        __syncthreads();

        #pragma unroll
        for (int k = 0; k < 32; k++) {
            float4 a = *(const float4*)&As[k][ty * 4];
            float wv[8];
            #pragma unroll
            for (int j = 0; j < 8; j++) wv[j] = Ws[k][tx + 16 * j];
            #pragma unroll
            for (int j = 0; j < 8; j++) {
                acc[0][j] += a.x * wv[j];
                acc[1][j] += a.y * wv[j];
                acc[2][j] += a.z * wv[j];
                acc[3][j] += a.w * wv[j];
            }
        }
        __syncthreads();
    }

    #pragma unroll
    for (int r = 0; r < 4; r++) {
        int grow = row0 + ty * 4 + r;
        if (grow < N_NODES) {
            float ds = g_din[grow];
            float os = SCALE_OUT ? g_dout[grow] : 1.0f;
            #pragma unroll
            for (int j = 0; j < 8; j++) {
                int c = tx + 16 * j;
                float v = acc[r][j] * ds + bias[c];
                if (RELU) v = fmaxf(v, 0.0f);
                out[(size_t)grow * D + c] = (OutT)(v * os);
            }
        }
    }
}

// ---------------------------------------------------------------------------
// Layer-3 pre-GEMM: Y[N,16] = A[N,128] @ W3[128,16]. W3 fully in smem.
// ---------------------------------------------------------------------------
__global__ __launch_bounds__(256)
void gemm16_kernel(const float* __restrict__ A,
                   const float* __restrict__ W3,
                   float* __restrict__ Y)
{
    __shared__ float Ws[128][20];    // padded: 80B row stride keeps float4 alignment
    int tid = threadIdx.x;
    for (int idx = tid; idx < 128 * 16; idx += 256) {
        int k = idx >> 4, c = idx & 15;
        Ws[k][c] = W3[idx];
    }
    __syncthreads();

    int row = blockIdx.x * 64 + (tid >> 2);
    int c4 = (tid & 3) << 2;
    if (row >= N_NODES) return;

    float4 acc = {0.f, 0.f, 0.f, 0.f};
    const float4* arow = (const float4*)(A + (size_t)row * D);
    #pragma unroll
    for (int kq = 0; kq < 32; kq++) {
        float4 a = arow[kq];
        float4 w0 = *(const float4*)&Ws[kq * 4 + 0][c4];
        float4 w1 = *(const float4*)&Ws[kq * 4 + 1][c4];
        float4 w2 = *(const float4*)&Ws[kq * 4 + 2][c4];
        float4 w3 = *(const float4*)&Ws[kq * 4 + 3][c4];
        acc.x += a.x * w0.x + a.y * w1.x + a.z * w2.x + a.w * w3.x;
        acc.y += a.x * w0.y + a.y * w1.y + a.z * w2.y + a.w * w3.y;
        acc.z += a.x * w0.z + a.y * w1.z + a.z * w2.z + a.w * w3.z;
        acc.w += a.x * w0.w + a.y * w1.w + a.z * w2.w + a.w * w3.w;
    }
    *(float4*)(Y + (size_t)row * 16 + c4) = acc;
}

// ---------------------------------------------------------------------------
// 16-wide aggregation + epilogue: out[n] = din[n] * segsum(Y[src]) + b3.
// ---------------------------------------------------------------------------
__global__ void agg16_kernel(const float* __restrict__ Y,
                             const float* __restrict__ b3,
                             float* __restrict__ out)
{
    int tid = threadIdx.x;
    int node = blockIdx.x * 64 + (tid >> 2);
    int q = tid & 3;
    if (node >= N_NODES) return;
    int beg = g_offs[node];
    int end = g_offs[node + 1];

    float4 a0 = {0.f, 0.f, 0.f, 0.f};
    float4 a1 = a0;
    int i = beg;
    for (; i + 2 <= end; i += 2) {
        int s0 = g_csr_src[i + 0];
        int s1 = g_csr_src[i + 1];
        float4 v0 = ((const float4*)(Y + (size_t)s0 * 16))[q];
        float4 v1 = ((const float4*)(Y + (size_t)s1 * 16))[q];
        a0.x += v0.x; a0.y += v0.y; a0.z += v0.z; a0.w += v0.w;
        a1.x += v1.x; a1.y += v1.y; a1.z += v1.z; a1.w += v1.w;
    }
    if (i < end) {
        int s = g_csr_src[i];
        float4 v = ((const float4*)(Y + (size_t)s * 16))[q];
        a0.x += v.x; a0.y += v.y; a0.z += v.z; a0.w += v.w;
    }
    float dn = g_din[node];
    float4 bb = ((const float4*)b3)[q];
    float4 o;
    o.x = (a0.x + a1.x) * dn + bb.x;
    o.y = (a0.y + a1.y) * dn + bb.y;
    o.z = (a0.z + a1.z) * dn + bb.z;
    o.w = (a0.w + a1.w) * dn + bb.w;
    ((float4*)(out + (size_t)node * 16))[q] = o;
}

// ---------------------------------------------------------------------------
// Launch
// ---------------------------------------------------------------------------
extern "C" void kernel_launch(void* const* d_in, const int* in_sizes, int n_in,
                              void* d_out, int out_size) {
    const float* features = (const float*)d_in[0];
    const int*   src      = (const int*)d_in[1];
    const int*   dst      = (const int*)d_in[2];
    const float* W1       = (const float*)d_in[3];
    const float* b1       = (const float*)d_in[4];
    const float* W2       = (const float*)d_in[5];
    const float* b2       = (const float*)d_in[6];
    const float* W3       = (const float*)d_in[7];
    const float* b3       = (const float*)d_in[8];
    float* out = (float*)d_out;

    __half* h16_ptr;
    float*  h32_ptr;
    float*  agg_ptr;
    cudaGetSymbolAddress((void**)&h16_ptr, g_h16);
    cudaGetSymbolAddress((void**)&h32_ptr, g_h32);
    cudaGetSymbolAddress((void**)&agg_ptr, g_agg);

    const int T = 256;
    int nodeBlocks  = (N_NODES + T - 1) / T;
    int edgeBlocks  = (N_EDGES + T - 1) / T;
    int quadBlocks  = (N_NODES * (D / 4) + T - 1) / T;
    int aggBlocks   = (N_NODES * 32 + T - 1) / T;    // warp per node
    int gemmBlocks  = (N_NODES + 63) / 64;
    int rows64      = (N_NODES + 63) / 64;

    // CSR build + degrees
    deg_zero_kernel<<<nodeBlocks, T>>>();
    deg_count_kernel<<<edgeBlocks, T>>>(src, dst);
    scan_kernel<<<1, 1024>>>();
    fill_kernel<<<edgeBlocks, T>>>(src, dst);

    // ---- Layer 1 ----
    scale_kernel<<<quadBlocks, T>>>(features);                 // feat -> fp16 h (scaled)
    agg_kernel<<<aggBlocks, T>>>(h16_ptr);
    gemm128_kernel<true, true, __half><<<gemmBlocks, 256>>>(agg_ptr, W1, b1, h16_ptr);

    // ---- Layer 2 ----
    agg_kernel<<<aggBlocks, T>>>(h16_ptr);
    gemm128_kernel<true, true, float><<<gemmBlocks, 256>>>(agg_ptr, W2, b2, h32_ptr);

    // ---- Layer 3: GEMM first (16-wide), then aggregate ----
    gemm16_kernel<<<rows64, 256>>>(h32_ptr, W3, agg_ptr);      // Y stored in g_agg
    agg16_kernel<<<rows64, 256>>>(agg_ptr, b3, out);
}